// round 5
// baseline (speedup 1.0000x reference)
#include <cuda_runtime.h>

// CRF NLL: B=1024, T=4096, K=16
// d_in[0]=feats [B,T,K] f32, d_in[1]=tags [B,T] i32, d_in[2]=transitions [K,K] f32
// out: [B] f32
// Each 16-lane group runs TWO independent scan chains (elements b, b+512)
// interleaved in one instruction stream to hide the recurrence latency.

#define T_LEN 4096
#define KTAG 16
#define TILE 8
#define START_TAG 14
#define STOP_TAG 15
#define BHALF 512

__global__ __launch_bounds__(64, 1)
void crf_nll_kernel(const float* __restrict__ feats,
                    const int* __restrict__ tags,
                    const float* __restrict__ trans,
                    float* __restrict__ out) {
    __shared__ float sExpT[256];    // exp(trans[j][i])
    __shared__ float sLogT[256];    // trans[j][i]
    __shared__ float sP[8][16];     // 4 slots x 2 chains

    int tid = threadIdx.x;
    for (int i = tid; i < 256; i += 64) {
        float tv = trans[i];
        sLogT[i] = tv;
        sExpT[i] = __expf(tv);      // exp(-10000) -> 0: exact masking
    }

    int lane = tid & 31;
    int grp  = lane >> 4;
    int j    = lane & 15;           // owned state
    int warp = tid >> 5;
    int g    = warp * 2 + grp;      // slot 0..3
    int b0   = blockIdx.x * 4 + g;  // chain 0 element
    int b1   = b0 + BHALF;          // chain 1 element

    __syncthreads();

    float Mr[16];
    #pragma unroll
    for (int i = 0; i < 16; i++) Mr[i] = sExpT[j * 16 + i];
    float Mstop = sExpT[STOP_TAG * 16 + j];

    const float* fb0 = feats + (size_t)b0 * T_LEN * KTAG;
    const float* fb1 = feats + (size_t)b1 * T_LEN * KTAG;
    const int*   tp0 = tags  + (size_t)b0 * T_LEN;
    const int*   tp1 = tags  + (size_t)b1 * T_LEN;

    float* P0 = &sP[2 * g + 0][0];
    float* P1 = &sP[2 * g + 1][0];

    P0[j] = (j == START_TAG) ? 1.0f : 0.0f;
    P1[j] = (j == START_TAG) ? 1.0f : 0.0f;
    __syncthreads();

    int   esum0 = 0, esum1 = 0;          // exact pow2 scale accumulators
    float gold0 = 0.f, gold1 = 0.f;
    int   pt0 = START_TAG, pt1 = START_TAG;
    float pnew0 = 0.f, pnew1 = 0.f;
    float sm0 = 1.0f, sm1 = 1.0f;        // stale maxima (measured 2 steps early)

    float e0A[TILE], e0B[TILE], e1A[TILE], e1B[TILE];
    int   t0A[TILE], t0B[TILE], t1A[TILE], t1B[TILE];

    // prime first tile: exp at prefetch time (off the scan chain)
    #pragma unroll
    for (int u = 0; u < TILE; u++) {
        e0A[u] = __expf(fb0[u * KTAG + j]);
        e1A[u] = __expf(fb1[u * KTAG + j]);
    }
    {
        const int4* q0 = reinterpret_cast<const int4*>(tp0);
        const int4* q1 = reinterpret_cast<const int4*>(tp1);
        #pragma unroll
        for (int q = 0; q < TILE / 4; q++) {
            int4 v = q0[q];
            t0A[4*q+0]=v.x; t0A[4*q+1]=v.y; t0A[4*q+2]=v.z; t0A[4*q+3]=v.w;
            int4 w = q1[q];
            t1A[4*q+0]=w.x; t1A[4*q+1]=w.y; t1A[4*q+2]=w.z; t1A[4*q+3]=w.w;
        }
    }

    const int NT = T_LEN / TILE;    // 512
    #pragma unroll 1
    for (int tile = 0; tile < NT; tile++) {
        if (tile + 1 < NT) {
            int base = (tile + 1) * TILE;
            #pragma unroll
            for (int u = 0; u < TILE; u++) {
                e0B[u] = __expf(fb0[(base + u) * KTAG + j]);
                e1B[u] = __expf(fb1[(base + u) * KTAG + j]);
            }
            const int4* q0 = reinterpret_cast<const int4*>(tp0 + base);
            const int4* q1 = reinterpret_cast<const int4*>(tp1 + base);
            #pragma unroll
            for (int q = 0; q < TILE / 4; q++) {
                int4 v = q0[q];
                t0B[4*q+0]=v.x; t0B[4*q+1]=v.y; t0B[4*q+2]=v.z; t0B[4*q+3]=v.w;
                int4 w = q1[q];
                t1B[4*q+0]=w.x; t1B[4*q+1]=w.y; t1B[4*q+2]=w.z; t1B[4*q+3]=w.w;
            }
        }
        int tbase = tile * TILE;

        #pragma unroll
        for (int u = 0; u < TILE; u++) {
            float ef0 = e0A[u], ef1 = e1A[u];
            int   tg0 = t0A[u], tg1 = t1A[u];

            // apply stale renorm: scale is a register known 2 steps early
            if ((u & 3) == 3) {
                int e0 = (__float_as_int(sm0) >> 23) & 255;
                ef0 *= __int_as_float((254 - e0) << 23);   // * 2^(127-e), exact
                esum0 += e0 - 127;
                int e1 = (__float_as_int(sm1) >> 23) & 255;
                ef1 *= __int_as_float((254 - e1) << 23);
                esum1 += e1 - 127;
            }

            __syncwarp();
            // broadcast both p vectors (conflict-free broadcast LDS.128)
            float4 a0 = *reinterpret_cast<const float4*>(P0 + 0);
            float4 a1 = *reinterpret_cast<const float4*>(P0 + 4);
            float4 a2 = *reinterpret_cast<const float4*>(P0 + 8);
            float4 a3 = *reinterpret_cast<const float4*>(P0 + 12);
            float4 c0 = *reinterpret_cast<const float4*>(P1 + 0);
            float4 c1 = *reinterpret_cast<const float4*>(P1 + 4);
            float4 c2 = *reinterpret_cast<const float4*>(P1 + 8);
            float4 c3 = *reinterpret_cast<const float4*>(P1 + 12);

            // measure maxima for use 2 steps later (off-chain FMNMX trees)
            if ((u & 3) == 1) {
                float m0 = fmaxf(fmaxf(fmaxf(a0.x,a0.y), fmaxf(a0.z,a0.w)),
                                 fmaxf(fmaxf(a1.x,a1.y), fmaxf(a1.z,a1.w)));
                float m1 = fmaxf(fmaxf(fmaxf(a2.x,a2.y), fmaxf(a2.z,a2.w)),
                                 fmaxf(fmaxf(a3.x,a3.y), fmaxf(a3.z,a3.w)));
                sm0 = fmaxf(m0, m1);
                float n0 = fmaxf(fmaxf(fmaxf(c0.x,c0.y), fmaxf(c0.z,c0.w)),
                                 fmaxf(fmaxf(c1.x,c1.y), fmaxf(c1.z,c1.w)));
                float n1 = fmaxf(fmaxf(fmaxf(c2.x,c2.y), fmaxf(c2.z,c2.w)),
                                 fmaxf(fmaxf(c3.x,c3.y), fmaxf(c3.z,c3.w)));
                sm1 = fmaxf(n0, n1);
            }

            // chain 0 matvec: tail FMA depends only on the last quad
            float x0 = fmaf(a3.x, Mr[12], fmaf(a2.x, Mr[ 8], fmaf(a1.x, Mr[4], a0.x * Mr[0])));
            float x1 = fmaf(a3.y, Mr[13], fmaf(a2.y, Mr[ 9], fmaf(a1.y, Mr[5], a0.y * Mr[1])));
            float x2 = fmaf(a3.z, Mr[14], fmaf(a2.z, Mr[10], fmaf(a1.z, Mr[6], a0.z * Mr[2])));
            float x3 = fmaf(a3.w, Mr[15], fmaf(a2.w, Mr[11], fmaf(a1.w, Mr[7], a0.w * Mr[3])));
            pnew0 = ((x0 + x1) + (x2 + x3)) * ef0;
            P0[j] = pnew0;

            // chain 1 matvec (independent -> fills chain 0's stall slots)
            float y0 = fmaf(c3.x, Mr[12], fmaf(c2.x, Mr[ 8], fmaf(c1.x, Mr[4], c0.x * Mr[0])));
            float y1 = fmaf(c3.y, Mr[13], fmaf(c2.y, Mr[ 9], fmaf(c1.y, Mr[5], c0.y * Mr[1])));
            float y2 = fmaf(c3.z, Mr[14], fmaf(c2.z, Mr[10], fmaf(c1.z, Mr[6], c0.z * Mr[2])));
            float y3 = fmaf(c3.w, Mr[15], fmaf(c2.w, Mr[11], fmaf(c1.w, Mr[7], c0.w * Mr[3])));
            pnew1 = ((y0 + y1) + (y2 + y3)) * ef1;
            P1[j] = pnew1;

            // gold scores (uniform L1-hot gathers + smem lookups, off chain)
            gold0 += fb0[(tbase + u) * KTAG + tg0] + sLogT[tg0 * 16 + pt0];
            pt0 = tg0;
            gold1 += fb1[(tbase + u) * KTAG + tg1] + sLogT[tg1 * 16 + pt1];
            pt1 = tg1;
        }

        #pragma unroll
        for (int u = 0; u < TILE; u++) {
            e0A[u] = e0B[u]; e1A[u] = e1B[u];
            t0A[u] = t0B[u]; t1A[u] = t1B[u];
        }
    }

    // forward_score = esum*ln2 + log( sum_j exp(trans[STOP,j]) * p_j )
    float v0 = Mstop * pnew0;
    float v1 = Mstop * pnew1;
    #pragma unroll
    for (int d = 1; d < 16; d <<= 1) {
        v0 += __shfl_xor_sync(0xffffffffu, v0, d, 16);
        v1 += __shfl_xor_sync(0xffffffffu, v1, d, 16);
    }

    double fwd0 = (double)esum0 * 0.6931471805599453 + (double)__logf(v0);
    double fwd1 = (double)esum1 * 0.6931471805599453 + (double)__logf(v1);
    float gT0 = gold0 + sLogT[STOP_TAG * 16 + pt0];
    float gT1 = gold1 + sLogT[STOP_TAG * 16 + pt1];

    if (j == 0) {
        out[b0] = (float)(fwd0 - (double)gT0);
        out[b1] = (float)(fwd1 - (double)gT1);
    }
}

extern "C" void kernel_launch(void* const* d_in, const int* in_sizes, int n_in,
                              void* d_out, int out_size) {
    const float* feats = (const float*)d_in[0];
    const int*   tags  = (const int*)d_in[1];
    const float* trans = (const float*)d_in[2];
    float* out = (float*)d_out;

    int B = in_sizes[1] / T_LEN;           // 1024
    int blocks = (B / 2) / 4;              // 128: 4 slots/block, 2 chains/slot
    crf_nll_kernel<<<blocks, 64>>>(feats, tags, trans, out);
}

// round 6
// speedup vs baseline: 1.2870x; 1.2870x over previous
#include <cuda_runtime.h>

// CRF NLL: B=1024, T=4096, K=16
// d_in[0]=feats [B,T,K] f32, d_in[1]=tags [B,T] i32, d_in[2]=transitions [K,K] f32
// out: [B] f32
//
// One 16-lane group per batch element; probability-domain scan with exact
// power-of-2 renormalization. Recurrence chain stripped to STS->LDS->FMA:
//  - no __syncwarp (lockstep 16-lane group, smem aliasing preserves order;
//    correctness of sync-free exchange validated in an earlier round)
//  - exp(feats) computed at prefetch time (MUFU off the chain)
//  - renorm scale measured 2 steps before it is applied (off the chain)

#define T_LEN 4096
#define KTAG 16
#define TILE 16
#define START_TAG 14
#define STOP_TAG 15

__global__ __launch_bounds__(128, 1)
void crf_nll_kernel(const float* __restrict__ feats,
                    const int* __restrict__ tags,
                    const float* __restrict__ trans,
                    float* __restrict__ out) {
    __shared__ float sExpT[256];   // exp(trans[j][i])
    __shared__ float sLogT[256];   // trans[j][i]
    __shared__ float sP[8][16];    // per-element probability vector

    int tid = threadIdx.x;
    for (int i = tid; i < 256; i += 128) {
        float tv = trans[i];
        sLogT[i] = tv;
        sExpT[i] = __expf(tv);     // exp(-10000) -> 0: correct masking
    }

    int lane = tid & 31;
    int grp  = lane >> 4;          // 2 batch elements per warp
    int j    = lane & 15;          // this thread owns state j
    int warp = tid >> 5;
    int g    = warp * 2 + grp;
    int b    = blockIdx.x * 8 + g;

    __syncthreads();

    float Mr[16];
    #pragma unroll
    for (int i = 0; i < 16; i++) Mr[i] = sExpT[j * 16 + i];
    float Mstop = sExpT[STOP_TAG * 16 + j];

    const float* fbase = feats + (size_t)b * T_LEN * KTAG;
    const int*   tptr  = tags  + (size_t)b * T_LEN;

    float* P = &sP[g][0];
    P[j] = (j == START_TAG) ? 1.0f : 0.0f;
    __syncthreads();

    int   esum = 0;          // exact power-of-2 scale accumulator
    float gold = 0.0f;
    int   prevtag = START_TAG;
    float pnew = 0.0f;
    float stale_m = 1.0f;    // max measured 2 steps before it is applied

    float eA[TILE], eB[TILE];  // exp(feat) for own state, precomputed
    int   gA[TILE], gB[TILE];

    // prime first tile (exp at prefetch: off the scan chain)
    #pragma unroll
    for (int u = 0; u < TILE; u++) eA[u] = __expf(fbase[u * KTAG + j]);
    {
        const int4* tp4 = reinterpret_cast<const int4*>(tptr);
        #pragma unroll
        for (int q = 0; q < 4; q++) {
            int4 v = tp4[q];
            gA[4*q+0] = v.x; gA[4*q+1] = v.y; gA[4*q+2] = v.z; gA[4*q+3] = v.w;
        }
    }

    const int NT = T_LEN / TILE;   // 256
    #pragma unroll 1
    for (int tile = 0; tile < NT; tile++) {
        if (tile + 1 < NT) {
            int base = (tile + 1) * TILE;
            #pragma unroll
            for (int u = 0; u < TILE; u++) eB[u] = __expf(fbase[(base + u) * KTAG + j]);
            const int4* tp4 = reinterpret_cast<const int4*>(tptr + base);
            #pragma unroll
            for (int q = 0; q < 4; q++) {
                int4 v = tp4[q];
                gB[4*q+0] = v.x; gB[4*q+1] = v.y; gB[4*q+2] = v.z; gB[4*q+3] = v.w;
            }
        }
        int tbase = tile * TILE;

        #pragma unroll
        for (int u = 0; u < TILE; u++) {
            float ef = eA[u];
            int   tg = gA[u];

            // apply stale renorm (register-resident scale, off chain)
            if ((u & 3) == 3) {
                int e = (__float_as_int(stale_m) >> 23) & 255;
                ef *= __int_as_float((254 - e) << 23);   // * 2^(127-e), exact
                esum += e - 127;
            }

            // broadcast p: plain (batchable) conflict-free LDS.128 x4.
            // No syncwarp: group is convergent; same-warp STS->LDS to the
            // same addresses is processed in issue order.
            float4 q0 = *reinterpret_cast<const float4*>(P + 0);
            float4 q1 = *reinterpret_cast<const float4*>(P + 4);
            float4 q2 = *reinterpret_cast<const float4*>(P + 8);
            float4 q3 = *reinterpret_cast<const float4*>(P + 12);

            // measure max for use 2 steps later (off-chain FMNMX tree)
            if ((u & 3) == 1) {
                float m0 = fmaxf(fmaxf(q0.x, q0.y), fmaxf(q0.z, q0.w));
                float m1 = fmaxf(fmaxf(q1.x, q1.y), fmaxf(q1.z, q1.w));
                float m2 = fmaxf(fmaxf(q2.x, q2.y), fmaxf(q2.z, q2.w));
                float m3 = fmaxf(fmaxf(q3.x, q3.y), fmaxf(q3.z, q3.w));
                stale_m = fmaxf(fmaxf(m0, m1), fmaxf(m2, m3));
            }

            // s_j = sum_i M[j,i] * p_i; tail depends only on last quad
            float a0 = fmaf(q3.x, Mr[12], fmaf(q2.x, Mr[ 8], fmaf(q1.x, Mr[4], q0.x * Mr[0])));
            float a1 = fmaf(q3.y, Mr[13], fmaf(q2.y, Mr[ 9], fmaf(q1.y, Mr[5], q0.y * Mr[1])));
            float a2 = fmaf(q3.z, Mr[14], fmaf(q2.z, Mr[10], fmaf(q1.z, Mr[6], q0.z * Mr[2])));
            float a3 = fmaf(q3.w, Mr[15], fmaf(q2.w, Mr[11], fmaf(q1.w, Mr[7], q0.w * Mr[3])));
            pnew = ((a0 + a1) + (a2 + a3)) * ef;
            P[j] = pnew;

            // gold score (uniform L1-hot gather + smem lookup, off chain)
            gold += fbase[(tbase + u) * KTAG + tg] + sLogT[tg * 16 + prevtag];
            prevtag = tg;
        }

        #pragma unroll
        for (int u = 0; u < TILE; u++) { eA[u] = eB[u]; gA[u] = gB[u]; }
    }

    // forward_score = esum*ln2 + log( sum_j exp(trans[STOP,j]) * p_j )
    float v = Mstop * pnew;
    v += __shfl_xor_sync(0xffffffffu, v, 1, 16);
    v += __shfl_xor_sync(0xffffffffu, v, 2, 16);
    v += __shfl_xor_sync(0xffffffffu, v, 4, 16);
    v += __shfl_xor_sync(0xffffffffu, v, 8, 16);

    double fwd = (double)esum * 0.6931471805599453 + (double)__logf(v);
    float goldT = gold + sLogT[STOP_TAG * 16 + prevtag];

    if (j == 0) out[b] = (float)(fwd - (double)goldT);
}

extern "C" void kernel_launch(void* const* d_in, const int* in_sizes, int n_in,
                              void* d_out, int out_size) {
    const float* feats = (const float*)d_in[0];
    const int*   tags  = (const int*)d_in[1];
    const float* trans = (const float*)d_in[2];
    float* out = (float*)d_out;

    int B = in_sizes[1] / T_LEN;           // 1024
    int blocks = B / 8;                    // 128 blocks x 128 threads
    crf_nll_kernel<<<blocks, 128>>>(feats, tags, trans, out);
}

// round 7
// speedup vs baseline: 1.8372x; 1.4275x over previous
#include <cuda_runtime.h>

// CRF NLL: B=1024, T=4096, K=16
// d_in[0]=feats [B,T,K] f32, d_in[1]=tags [B,T] i32, d_in[2]=transitions [K,K] f32
// out: [B] f32
//
// R2 winning skeleton (syncwarp smem exchange) with two off-chain transforms:
//  - exp(feats) computed at prefetch time (MUFU off the scan chain)
//  - exact pow2 renorm with scale measured 2 steps before application

#define T_LEN 4096
#define KTAG 16
#define TILE 16
#define START_TAG 14
#define STOP_TAG 15

__global__ __launch_bounds__(128, 1)
void crf_nll_kernel(const float* __restrict__ feats,
                    const int* __restrict__ tags,
                    const float* __restrict__ trans,
                    float* __restrict__ out) {
    __shared__ float sExpT[256];   // exp(trans[j][i])
    __shared__ float sLogT[256];   // trans[j][i]
    __shared__ float sP[8][16];    // per-element probability vector

    int tid = threadIdx.x;
    for (int i = tid; i < 256; i += 128) {
        float tv = trans[i];
        sLogT[i] = tv;
        sExpT[i] = __expf(tv);     // exp(-10000) -> 0: correct masking
    }

    int lane = tid & 31;
    int grp  = lane >> 4;          // 2 batch elements per warp
    int j    = lane & 15;          // this thread owns state j
    int warp = tid >> 5;
    int g    = warp * 2 + grp;
    int b    = blockIdx.x * 8 + g;

    __syncthreads();

    float Mr[16];
    #pragma unroll
    for (int i = 0; i < 16; i++) Mr[i] = sExpT[j * 16 + i];
    float Mstop = sExpT[STOP_TAG * 16 + j];

    const float* fbase = feats + (size_t)b * T_LEN * KTAG;
    const int*   tptr  = tags  + (size_t)b * T_LEN;

    float* P = &sP[g][0];
    P[j] = (j == START_TAG) ? 1.0f : 0.0f;
    __syncthreads();

    int   esum = 0;          // exact power-of-2 scale accumulator
    float gold = 0.0f;
    int   prevtag = START_TAG;
    float pnew = 0.0f;
    float stale_m = 1.0f;    // max measured 2 steps before it is applied

    float eA[TILE], eB[TILE];  // exp(feat) for own state, precomputed
    int   gA[TILE], gB[TILE];

    // prime first tile (exp at prefetch: off the scan chain)
    #pragma unroll
    for (int u = 0; u < TILE; u++) eA[u] = __expf(fbase[u * KTAG + j]);
    {
        const int4* tp4 = reinterpret_cast<const int4*>(tptr);
        #pragma unroll
        for (int q = 0; q < 4; q++) {
            int4 v = tp4[q];
            gA[4*q+0] = v.x; gA[4*q+1] = v.y; gA[4*q+2] = v.z; gA[4*q+3] = v.w;
        }
    }

    const int NT = T_LEN / TILE;   // 256
    #pragma unroll 1
    for (int tile = 0; tile < NT; tile++) {
        if (tile + 1 < NT) {
            int base = (tile + 1) * TILE;
            #pragma unroll
            for (int u = 0; u < TILE; u++) eB[u] = __expf(fbase[(base + u) * KTAG + j]);
            const int4* tp4 = reinterpret_cast<const int4*>(tptr + base);
            #pragma unroll
            for (int q = 0; q < 4; q++) {
                int4 v = tp4[q];
                gB[4*q+0] = v.x; gB[4*q+1] = v.y; gB[4*q+2] = v.z; gB[4*q+3] = v.w;
            }
        }
        int tbase = tile * TILE;

        #pragma unroll
        for (int u = 0; u < TILE; u++) {
            float ef = eA[u];
            int   tg = gA[u];

            // apply stale renorm: scale is register-resident well before the
            // LDS of this step returns -> off the critical chain
            if ((u & 3) == 3) {
                int e = (__float_as_int(stale_m) >> 23) & 255;
                ef *= __int_as_float((254 - e) << 23);   // * 2^(127-e), exact
                esum += e - 127;
            }

            // broadcast p via smem (R2 winning exchange)
            __syncwarp();
            float4 q0 = *reinterpret_cast<const float4*>(P + 0);
            float4 q1 = *reinterpret_cast<const float4*>(P + 4);
            float4 q2 = *reinterpret_cast<const float4*>(P + 8);
            float4 q3 = *reinterpret_cast<const float4*>(P + 12);

            // measure max for use 2 steps later (result not needed now ->
            // FMNMX tree runs in the shadow of the matvec)
            if ((u & 3) == 1) {
                float m0 = fmaxf(fmaxf(q0.x, q0.y), fmaxf(q0.z, q0.w));
                float m1 = fmaxf(fmaxf(q1.x, q1.y), fmaxf(q1.z, q1.w));
                float m2 = fmaxf(fmaxf(q2.x, q2.y), fmaxf(q2.z, q2.w));
                float m3 = fmaxf(fmaxf(q3.x, q3.y), fmaxf(q3.z, q3.w));
                stale_m = fmaxf(fmaxf(m0, m1), fmaxf(m2, m3));
            }

            // s_j = sum_i M[j,i] * p_i; tail FMA depends only on last quad
            float a0 = fmaf(q3.x, Mr[12], fmaf(q2.x, Mr[ 8], fmaf(q1.x, Mr[4], q0.x * Mr[0])));
            float a1 = fmaf(q3.y, Mr[13], fmaf(q2.y, Mr[ 9], fmaf(q1.y, Mr[5], q0.y * Mr[1])));
            float a2 = fmaf(q3.z, Mr[14], fmaf(q2.z, Mr[10], fmaf(q1.z, Mr[6], q0.z * Mr[2])));
            float a3 = fmaf(q3.w, Mr[15], fmaf(q2.w, Mr[11], fmaf(q1.w, Mr[7], q0.w * Mr[3])));
            pnew = ((a0 + a1) + (a2 + a3)) * ef;
            P[j] = pnew;

            // gold score (uniform L1-hot gather + smem lookup, off chain)
            gold += fbase[(tbase + u) * KTAG + tg] + sLogT[tg * 16 + prevtag];
            prevtag = tg;
        }

        #pragma unroll
        for (int u = 0; u < TILE; u++) { eA[u] = eB[u]; gA[u] = gB[u]; }
    }

    // forward_score = esum*ln2 + log( sum_j exp(trans[STOP,j]) * p_j )
    float v = Mstop * pnew;
    v += __shfl_xor_sync(0xffffffffu, v, 1, 16);
    v += __shfl_xor_sync(0xffffffffu, v, 2, 16);
    v += __shfl_xor_sync(0xffffffffu, v, 4, 16);
    v += __shfl_xor_sync(0xffffffffu, v, 8, 16);

    double fwd = (double)esum * 0.6931471805599453 + (double)__logf(v);
    float goldT = gold + sLogT[STOP_TAG * 16 + prevtag];

    if (j == 0) out[b] = (float)(fwd - (double)goldT);
}

extern "C" void kernel_launch(void* const* d_in, const int* in_sizes, int n_in,
                              void* d_out, int out_size) {
    const float* feats = (const float*)d_in[0];
    const int*   tags  = (const int*)d_in[1];
    const float* trans = (const float*)d_in[2];
    float* out = (float*)d_out;

    int B = in_sizes[1] / T_LEN;           // 1024
    int blocks = B / 8;                    // 128 blocks x 128 threads
    crf_nll_kernel<<<blocks, 128>>>(feats, tags, trans, out);
}

// round 8
// speedup vs baseline: 1.9541x; 1.0636x over previous
#include <cuda_runtime.h>

// CRF NLL: B=1024, T=4096, K=16
// d_in[0]=feats [B,T,K] f32, d_in[1]=tags [B,T] i32, d_in[2]=transitions [K,K] f32
// out: [B] f32
//
// R2 winning step body, unchanged. Layout change only: ONE batch element per
// warp; lanes 16-31 mirror lanes 0-15 (fully converged, idempotent smem
// stores). Halves per-warp in-order issue per step and lets ~2 warps/SMSP
// interleave.

#define T_LEN 4096
#define KTAG 16
#define TILE 16
#define START_TAG 14
#define STOP_TAG 15

__global__ __launch_bounds__(128, 2)
void crf_nll_kernel(const float* __restrict__ feats,
                    const int* __restrict__ tags,
                    const float* __restrict__ trans,
                    float* __restrict__ out) {
    __shared__ float sExpT[256];   // exp(trans[j][i])
    __shared__ float sLogT[256];   // trans[j][i]
    __shared__ float sP[4][16];    // one probability vector per warp

    int tid = threadIdx.x;
    for (int i = tid; i < 256; i += 128) {
        float tv = trans[i];
        sLogT[i] = tv;
        sExpT[i] = __expf(tv);     // exp(-10000) -> 0: correct masking
    }

    int lane = tid & 31;
    int j    = lane & 15;          // owned state; lanes 16-31 mirror 0-15
    int warp = tid >> 5;
    int b    = blockIdx.x * 4 + warp;   // one element per warp

    __syncthreads();

    float Mr[16];
    #pragma unroll
    for (int i = 0; i < 16; i++) Mr[i] = sExpT[j * 16 + i];
    float Mstop = sExpT[STOP_TAG * 16 + j];

    const float* fbase = feats + (size_t)b * T_LEN * KTAG;
    const int*   tptr  = tags  + (size_t)b * T_LEN;

    float* P = &sP[warp][0];
    P[j] = (j == START_TAG) ? 1.0f : 0.0f;   // both halves write same value
    __syncthreads();

    int   esum = 0;          // exact power-of-2 scale accumulator
    float gold = 0.0f;
    int   prevtag = START_TAG;
    float pnew = 0.0f;

    float fA[TILE], fB[TILE];
    int   gA[TILE], gB[TILE];

    // prime first tile
    #pragma unroll
    for (int u = 0; u < TILE; u++) fA[u] = fbase[u * KTAG + j];
    {
        const int4* tp4 = reinterpret_cast<const int4*>(tptr);
        #pragma unroll
        for (int q = 0; q < 4; q++) {
            int4 v = tp4[q];
            gA[4*q+0] = v.x; gA[4*q+1] = v.y; gA[4*q+2] = v.z; gA[4*q+3] = v.w;
        }
    }

    const int NT = T_LEN / TILE;   // 256
    #pragma unroll 1
    for (int tile = 0; tile < NT; tile++) {
        if (tile + 1 < NT) {
            int base = (tile + 1) * TILE;
            #pragma unroll
            for (int u = 0; u < TILE; u++) fB[u] = fbase[(base + u) * KTAG + j];
            const int4* tp4 = reinterpret_cast<const int4*>(tptr + base);
            #pragma unroll
            for (int q = 0; q < 4; q++) {
                int4 v = tp4[q];
                gB[4*q+0] = v.x; gB[4*q+1] = v.y; gB[4*q+2] = v.z; gB[4*q+3] = v.w;
            }
        }
        int tbase = tile * TILE;

        #pragma unroll
        for (int u = 0; u < TILE; u++) {
            float f  = fA[u];
            int   tg = gA[u];
            float ef = __expf(f);

            // broadcast p via smem (R2 winning exchange)
            __syncwarp();
            float4 q0 = *reinterpret_cast<const float4*>(P + 0);
            float4 q1 = *reinterpret_cast<const float4*>(P + 4);
            float4 q2 = *reinterpret_cast<const float4*>(P + 8);
            float4 q3 = *reinterpret_cast<const float4*>(P + 12);

            // exact pow2 renorm every 4 steps (R2 structure)
            if ((u & 3) == 3) {
                float m0 = fmaxf(fmaxf(q0.x, q0.y), fmaxf(q0.z, q0.w));
                float m1 = fmaxf(fmaxf(q1.x, q1.y), fmaxf(q1.z, q1.w));
                float m2 = fmaxf(fmaxf(q2.x, q2.y), fmaxf(q2.z, q2.w));
                float m3 = fmaxf(fmaxf(q3.x, q3.y), fmaxf(q3.z, q3.w));
                float m  = fmaxf(fmaxf(m0, m1), fmaxf(m2, m3));
                int e = (__float_as_int(m) >> 23) & 255;
                ef *= __int_as_float((254 - e) << 23);   // * 2^(127-e), exact
                esum += e - 127;
            }

            // s_j = sum_i M[j,i] * p_i; tail FMA depends only on last quad
            float a0 = fmaf(q3.x, Mr[12], fmaf(q2.x, Mr[ 8], fmaf(q1.x, Mr[4], q0.x * Mr[0])));
            float a1 = fmaf(q3.y, Mr[13], fmaf(q2.y, Mr[ 9], fmaf(q1.y, Mr[5], q0.y * Mr[1])));
            float a2 = fmaf(q3.z, Mr[14], fmaf(q2.z, Mr[10], fmaf(q1.z, Mr[6], q0.z * Mr[2])));
            float a3 = fmaf(q3.w, Mr[15], fmaf(q2.w, Mr[11], fmaf(q1.w, Mr[7], q0.w * Mr[3])));
            pnew = ((a0 + a1) + (a2 + a3)) * ef;
            P[j] = pnew;

            // gold score (single uniform L1-hot gather per warp now)
            gold += fbase[(tbase + u) * KTAG + tg] + sLogT[tg * 16 + prevtag];
            prevtag = tg;
        }

        #pragma unroll
        for (int u = 0; u < TILE; u++) { fA[u] = fB[u]; gA[u] = gB[u]; }
    }

    // forward_score = esum*ln2 + log( sum_j exp(trans[STOP,j]) * p_j )
    float v = Mstop * pnew;
    v += __shfl_xor_sync(0xffffffffu, v, 1, 16);
    v += __shfl_xor_sync(0xffffffffu, v, 2, 16);
    v += __shfl_xor_sync(0xffffffffu, v, 4, 16);
    v += __shfl_xor_sync(0xffffffffu, v, 8, 16);

    double fwd = (double)esum * 0.6931471805599453 + (double)__logf(v);
    float goldT = gold + sLogT[STOP_TAG * 16 + prevtag];

    if (lane == 0) out[b] = (float)(fwd - (double)goldT);
}

extern "C" void kernel_launch(void* const* d_in, const int* in_sizes, int n_in,
                              void* d_out, int out_size) {
    const float* feats = (const float*)d_in[0];
    const int*   tags  = (const int*)d_in[1];
    const float* trans = (const float*)d_in[2];
    float* out = (float*)d_out;

    int B = in_sizes[1] / T_LEN;           // 1024
    int blocks = B / 4;                    // 256 blocks x 4 warps, 1 elem/warp
    crf_nll_kernel<<<blocks, 128>>>(feats, tags, trans, out);
}